// round 1
// baseline (speedup 1.0000x reference)
#include <cuda_runtime.h>
#include <cstdint>

#define BB 2
#define LL 2048
#define DD 1024
#define HH 16
#define DH 64
#define L3 3072

// ---------------- scratch (device globals; no allocations) ----------------
__device__ float g_qkv[(size_t)BB * LL * L3];        // [B*L, 3D]  50 MB
__device__ float g_w[(size_t)BB * HH * LL * LL];     // weights [B,H,Lq,Lk] 537 MB
__device__ float g_ctx[(size_t)BB * LL * DD];        // combined context [B*L, D] 16 MB

// ---------------- generic 128x128x8 SGEMM: C = A(MxK) @ B(KxN) -------------
__global__ __launch_bounds__(256) void sgemm_kernel(
    const float* __restrict__ A, const float* __restrict__ B,
    float* __restrict__ C, int M, int N, int K)
{
    __shared__ float As[8][128];
    __shared__ float Bs[8][128];
    const int t  = threadIdx.x;
    const int bm = blockIdx.y * 128;
    const int bn = blockIdx.x * 128;
    const int tx = t & 15, ty = t >> 4;

    float c[8][8];
#pragma unroll
    for (int i = 0; i < 8; i++)
#pragma unroll
        for (int j = 0; j < 8; j++) c[i][j] = 0.f;

    const int arow = t >> 1, ako = (t & 1) * 4;
    const int brow = t >> 5, bno = (t & 31) * 4;

    for (int kt = 0; kt < K; kt += 8) {
        float4 av = *(const float4*)(A + (size_t)(bm + arow) * K + kt + ako);
        float4 bv = *(const float4*)(B + (size_t)(kt + brow) * N + bn + bno);
        As[ako + 0][arow] = av.x;
        As[ako + 1][arow] = av.y;
        As[ako + 2][arow] = av.z;
        As[ako + 3][arow] = av.w;
        *(float4*)&Bs[brow][bno] = bv;
        __syncthreads();
#pragma unroll
        for (int kk = 0; kk < 8; kk++) {
            float a[8], b[8];
            *(float4*)&a[0] = *(const float4*)&As[kk][ty * 8];
            *(float4*)&a[4] = *(const float4*)&As[kk][ty * 8 + 4];
            *(float4*)&b[0] = *(const float4*)&Bs[kk][tx * 8];
            *(float4*)&b[4] = *(const float4*)&Bs[kk][tx * 8 + 4];
#pragma unroll
            for (int i = 0; i < 8; i++)
#pragma unroll
                for (int j = 0; j < 8; j++) c[i][j] += a[i] * b[j];
        }
        __syncthreads();
    }
#pragma unroll
    for (int i = 0; i < 8; i++) {
        float* crow = C + (size_t)(bm + ty * 8 + i) * N + bn + tx * 8;
        *(float4*)(crow)     = make_float4(c[i][0], c[i][1], c[i][2], c[i][3]);
        *(float4*)(crow + 4) = make_float4(c[i][4], c[i][5], c[i][6], c[i][7]);
    }
}

// ------------- fused QK^T + bias + softmax + weight/align writes ------------
// grid: (L/16, H, B), 256 threads, dyn smem: S[16][2048] + Qs[16][64] + Ks[256][65]
#define QK_SMEM_FLOATS (16 * 2048 + 16 * 64 + 256 * 65)
#define QK_SMEM_BYTES  (QK_SMEM_FLOATS * 4)

__global__ __launch_bounds__(256) void qk_softmax_kernel(
    const float* __restrict__ qkv, const float* __restrict__ bias,
    float* __restrict__ wout, float* __restrict__ align, int write_align)
{
    extern __shared__ float sm[];
    float* S  = sm;                 // [16][2048]
    float* Qs = sm + 16 * 2048;     // [16][64]
    float* Ks = Qs + 16 * 64;       // [256][65] padded

    const int t  = threadIdx.x;
    const int q0 = blockIdx.x * 16;
    const int h  = blockIdx.y;
    const int b  = blockIdx.z;

    // load Q tile (scaled by DH^-0.5 = 0.125)
    {
        int row = t >> 4, dd = (t & 15) * 4;
        float4 v = *(const float4*)(qkv + (size_t)(b * LL + q0 + row) * L3 + h * DH + dd);
        v.x *= 0.125f; v.y *= 0.125f; v.z *= 0.125f; v.w *= 0.125f;
        *(float4*)(Qs + row * DH + dd) = v;
    }

    const int c0 = t & 127;        // column-in-tile (two columns: c0, c0+128)
    const int rg = (t >> 7) * 8;   // row group: 0 or 8

    for (int jt = 0; jt < LL; jt += 256) {
        __syncthreads();
        // load K tile 256x64 into padded smem
#pragma unroll
        for (int k = 0; k < 16; k++) {
            int i4  = t + k * 256;
            int row = i4 >> 4, dd = (i4 & 15) * 4;
            float4 v = *(const float4*)(qkv + (size_t)(b * LL + jt + row) * L3 + DD + h * DH + dd);
            float* kr = Ks + row * 65 + dd;
            kr[0] = v.x; kr[1] = v.y; kr[2] = v.z; kr[3] = v.w;
        }
        __syncthreads();

        const float* Kr0 = Ks + c0 * 65;
        const float* Kr1 = Ks + (c0 + 128) * 65;
        float acc0[8], acc1[8];
#pragma unroll
        for (int r = 0; r < 8; r++) { acc0[r] = 0.f; acc1[r] = 0.f; }

#pragma unroll
        for (int d = 0; d < DH; d += 4) {
            float4 q[8];
#pragma unroll
            for (int r = 0; r < 8; r++)
                q[r] = *(const float4*)(Qs + (rg + r) * DH + d);
#pragma unroll
            for (int dd = 0; dd < 4; dd++) {
                float ka = Kr0[d + dd];
                float kb = Kr1[d + dd];
#pragma unroll
                for (int r = 0; r < 8; r++) {
                    float qv = (&q[r].x)[dd];
                    acc0[r] += qv * ka;
                    acc1[r] += qv * kb;
                }
            }
        }
#pragma unroll
        for (int r = 0; r < 8; r++) {
            S[(rg + r) * LL + jt + c0]       = acc0[r];
            S[(rg + r) * LL + jt + c0 + 128] = acc1[r];
        }
    }
    __syncthreads();

    // softmax (rows 0..15, one row per warp round)
    {
        const int warp = t >> 5, lane = t & 31;
        const float* brow = bias + (size_t)b * LL;
        for (int r = warp; r < 16; r += 8) {
            float* Sr = S + r * LL;
            float m = -1e30f;
            for (int j = lane; j < LL; j += 32) m = fmaxf(m, Sr[j] + brow[j]);
#pragma unroll
            for (int o = 16; o; o >>= 1) m = fmaxf(m, __shfl_xor_sync(0xffffffffu, m, o));
            float sum = 0.f;
            for (int j = lane; j < LL; j += 32) {
                float e = __expf(Sr[j] + brow[j] - m);
                Sr[j] = e;
                sum += e;
            }
#pragma unroll
            for (int o = 16; o; o >>= 1) sum += __shfl_xor_sync(0xffffffffu, sum, o);
            float inv = 1.0f / sum;
            for (int j = lane; j < LL; j += 32) Sr[j] *= inv;
        }
    }
    __syncthreads();

    // write weights [b,h,q0+r, :] to scratch (coalesced)
    {
        float* wp = wout + ((size_t)(b * HH + h) * LL + q0) * LL;
#pragma unroll
        for (int k = 0; k < 32; k++) {
            int i4 = t + k * 256;             // 16*512 float4s
            int r  = i4 >> 9;
            int c4 = (i4 & 511) << 2;
            *(float4*)(wp + (size_t)r * LL + c4) = *(const float4*)(S + r * LL + c4);
        }
    }
    // write align [b,h,j, q0..q0+16) (transposed; float4 along q)
    if (write_align) {
        float* ap = align + (size_t)(b * HH + h) * LL * LL;
#pragma unroll
        for (int k = 0; k < 32; k++) {
            int i4  = t + k * 256;            // 2048 j * 4 groups
            int j   = i4 >> 2;
            int rg4 = (i4 & 3) * 4;
            float4 v;
            v.x = S[(rg4 + 0) * LL + j];
            v.y = S[(rg4 + 1) * LL + j];
            v.z = S[(rg4 + 2) * LL + j];
            v.w = S[(rg4 + 3) * LL + j];
            *(float4*)(ap + (size_t)j * LL + q0 + rg4) = v;
        }
    }
}

// ---------------- PV: ctx[b,q, h*64+d] = W[b,h,q,:] @ V[b,:,h,d] ------------
// grid: (L/128, H, B), 256 threads, tiles 128(q) x 64(d) x 32(k)
__global__ __launch_bounds__(256) void pv_kernel(
    const float* __restrict__ qkv, const float* __restrict__ w,
    float* __restrict__ ctx)
{
    __shared__ float Ws[32][128];  // transposed: Ws[k][q]
    __shared__ float Vs[32][64];

    const int t  = threadIdx.x;
    const int qt = blockIdx.x;
    const int h  = blockIdx.y;
    const int b  = blockIdx.z;
    const size_t wbase = ((size_t)(b * HH + h) * LL + qt * 128) * LL;

    const int tx = t & 15, ty = t >> 4;
    float c[8][4];
#pragma unroll
    for (int i = 0; i < 8; i++)
#pragma unroll
        for (int j = 0; j < 4; j++) c[i][j] = 0.f;

    for (int kt = 0; kt < LL; kt += 32) {
#pragma unroll
        for (int k = 0; k < 4; k++) {
            int i4 = t + k * 256;
            int q = i4 >> 3, ko = (i4 & 7) * 4;
            float4 v = *(const float4*)(w + wbase + (size_t)q * LL + kt + ko);
            Ws[ko + 0][q] = v.x;
            Ws[ko + 1][q] = v.y;
            Ws[ko + 2][q] = v.z;
            Ws[ko + 3][q] = v.w;
        }
#pragma unroll
        for (int k = 0; k < 2; k++) {
            int i4  = t + k * 256;
            int row = i4 >> 4, dd = (i4 & 15) * 4;
            float4 v = *(const float4*)(qkv + (size_t)(b * LL + kt + row) * L3 + 2 * DD + h * DH + dd);
            *(float4*)&Vs[row][dd] = v;
        }
        __syncthreads();
#pragma unroll
        for (int kk = 0; kk < 32; kk++) {
            float a[8], bb[4];
            *(float4*)&a[0]  = *(const float4*)&Ws[kk][ty * 8];
            *(float4*)&a[4]  = *(const float4*)&Ws[kk][ty * 8 + 4];
            *(float4*)&bb[0] = *(const float4*)&Vs[kk][tx * 4];
#pragma unroll
            for (int i = 0; i < 8; i++)
#pragma unroll
                for (int j = 0; j < 4; j++) c[i][j] += a[i] * bb[j];
        }
        __syncthreads();
    }
#pragma unroll
    for (int i = 0; i < 8; i++) {
        size_t o = ((size_t)(b * LL) + qt * 128 + ty * 8 + i) * DD + h * DH + tx * 4;
        *(float4*)(ctx + o) = make_float4(c[i][0], c[i][1], c[i][2], c[i][3]);
    }
}

// --------------------------------- launch ----------------------------------
extern "C" void kernel_launch(void* const* d_in, const int* in_sizes, int n_in,
                              void* d_out, int out_size)
{
    const float* queries = (const float*)d_in[0];
    const float* bias    = (const float*)d_in[1];
    const float* w_qkv   = (const float*)d_in[2];
    const float* w_o     = (const float*)d_in[3];
    float* out = (float*)d_out;

    const size_t out_elems   = (size_t)BB * LL * DD;        // 4,194,304
    const size_t align_elems = (size_t)BB * HH * LL * LL;   // 134,217,728
    int write_align = ((size_t)out_size >= out_elems + align_elems) ? 1 : 0;
    float* align = out + out_elems;

    float *qkv_p = nullptr, *w_p = nullptr, *ctx_p = nullptr;
    cudaGetSymbolAddress((void**)&qkv_p, g_qkv);
    cudaGetSymbolAddress((void**)&w_p,   g_w);
    cudaGetSymbolAddress((void**)&ctx_p, g_ctx);

    cudaFuncSetAttribute(qk_softmax_kernel,
                         cudaFuncAttributeMaxDynamicSharedMemorySize, QK_SMEM_BYTES);

    // 1) QKV projection: [4096,1024] @ [1024,3072]
    {
        dim3 grid(L3 / 128, (BB * LL) / 128);
        sgemm_kernel<<<grid, 256>>>(queries, w_qkv, qkv_p, BB * LL, L3, DD);
    }
    // 2) QK^T + bias + softmax + weights/align
    {
        dim3 grid(LL / 16, HH, BB);
        qk_softmax_kernel<<<grid, 256, QK_SMEM_BYTES>>>(qkv_p, bias, w_p, align, write_align);
    }
    // 3) PV -> combined context
    {
        dim3 grid(LL / 128, HH, BB);
        pv_kernel<<<grid, 256>>>(qkv_p, w_p, ctx_p);
    }
    // 4) output projection: [4096,1024] @ [1024,1024]
    {
        dim3 grid(DD / 128, (BB * LL) / 128);
        sgemm_kernel<<<grid, 256>>>(ctx_p, w_o, out, BB * LL, DD, DD);
    }
}